// round 14
// baseline (speedup 1.0000x reference)
#include <cuda_runtime.h>
#include <cuda_fp16.h>
#include <mma.h>
#include <cstdint>

using namespace nvcuda;

#define BB 4
#define NN 4096
#define DIMV 128
#define DE 512
#define TOT (BB * NN)          // 16384 rows
#define CHUNK 16
#define NCHUNK (NN / CHUNK)    // 256

// Scratch (allocation-free: __device__ globals)
// Channel permutation: p=2d <-> orig d (lo), p=2d+1 <-> orig d+256 (hi).
// g_sh_h per row (fp16): [0,512) = sigmoid(s) gate (perm), [512,1024) = combined
//   where combined[2d] = gelu(h_d), combined[2d+1] = gelu(h_d)*gelu(h_{d+256}).
__device__ __half g_sh_h[(size_t)TOT * 1024];
__device__ __half g_o_h[(size_t)TOT * DE];    // gated aggregation (fp16, perm order)
// g_part layout: [b][p][c]  (p-major; c contiguous)
__device__ float  g_part[BB * DE * NCHUNK];
__device__ __half g_xq_h[(size_t)TOT * DIMV]; // fp16 copy of xq
__device__ __half g_w1_h[1024 * DIMV];        // [W_se; W_po] fp16, rows permuted
__device__ __half g_w3_h[DIMV * DE];          // W_ag fp16, K-dim permuted
__device__ float  g_b1[1024];                 // [b_se; b_po] permuted

#define BM 128
#define BKG 32
#define PADH 40                 // half pitch: 80 B, multiple of 16

__device__ __forceinline__ float gelu_exact(float x) {
    return 0.5f * x * (1.0f + erff(x * 0.70710678118654752f));
}
__device__ __forceinline__ float sigmoid_f(float x) {
    return 1.0f / (1.0f + expf(-x));
}
__device__ __forceinline__ int perm_orig(int p) {     // permuted -> original channel
    return (p & 1) ? 256 + (p >> 1) : (p >> 1);
}

__device__ __forceinline__ void cp_async16(void* smem_dst, const void* gmem_src) {
    unsigned s = (unsigned)__cvta_generic_to_shared(smem_dst);
    asm volatile("cp.async.cg.shared.global [%0], [%1], 16;" :: "r"(s), "l"(gmem_src));
}
__device__ __forceinline__ void cp_commit() {
    asm volatile("cp.async.commit_group;");
}
template <int N>
__device__ __forceinline__ void cp_wait() {
    asm volatile("cp.async.wait_group %0;" :: "n"(N));
}

// ---------------------------------------------------------------------------
// Merged conversion kernel (one launch) — applies the channel permutation.
// ---------------------------------------------------------------------------
__global__ __launch_bounds__(256) void conv_all_kernel(
    const float* __restrict__ x,
    const float* __restrict__ wse, const float* __restrict__ wpo,
    const float* __restrict__ wag,
    const float* __restrict__ bse, const float* __restrict__ bpo)
{
    int i = blockIdx.x * 256 + threadIdx.x;    // grid: 2048*256 = 524288
    {   // xq: 2,097,152 elems = 524,288 float4 slots
        int e = i * 4;
        float4 v = *reinterpret_cast<const float4*>(&x[e]);
        *reinterpret_cast<__half2*>(&g_xq_h[e])     = __floats2half2_rn(v.x, v.y);
        *reinterpret_cast<__half2*>(&g_xq_h[e + 2]) = __floats2half2_rn(v.z, v.w);
    }
    if (i < 65536) {
        {   // W_se / W_po: permuted rows. i = r*128 + k
            int r = i >> 7, k = i & 127;
            int po = perm_orig(r);
            g_w1_h[i]         = __float2half(wse[po * 128 + k]);
            g_w1_h[65536 + i] = __float2half(wpo[po * 128 + k]);
        }
        {   // W_ag: permuted K. i = j*512 + p
            int j = i >> 9, p = i & 511;
            g_w3_h[i] = __float2half(wag[j * 512 + perm_orig(p)]);
        }
        if (i < 512) {
            int po = perm_orig(i);
            g_b1[i] = bse[po]; g_b1[512 + i] = bpo[po];
        }
    }
}

// ---------------------------------------------------------------------------
// fp16 wmma GEMM (fp32 accum), BM=128 x BN tile, BK=32, NST-stage cp.async.
// 256 threads = 8 warps (4 M x 2 N); warp tile 32 x (BN/2).
// op: 0=none 1=sigmoid 2=gelu+pair-combine (+ fused per-chunk column sums
//     into g_part — each (chunk,p) owned by exactly one warp).
// ---------------------------------------------------------------------------
template <int BN, int NST, typename OutT>
__global__ __launch_bounds__(256) void gemm_f16_kernel(
    const __half* __restrict__ A, int lda,
    const __half* __restrict__ W, const float* __restrict__ bias,
    int op0, int op1, int opSplit, int K,
    OutT* __restrict__ out, int ldo)
{
    constexpr int NF  = BN / 32;
    constexpr int STG = (BM + BN) * PADH;
    __shared__ __half smem_all[NST * STG];

    const int m0 = blockIdx.x * BM;
    const int j0 = blockIdx.y * BN;
    const int op = (j0 < opSplit) ? op0 : op1;

    const int tid  = threadIdx.x;
    const int warp = tid >> 5;
    const int lane = tid & 31;
    const int wm = (warp & 3) * 32;
    const int wn = (warp >> 2) * (BN / 2);

    const int niters = K / BKG;

    auto issue_load = [&](int it, int buf) {
        __half* sa = smem_all + buf * STG;
        __half* sb = sa + BM * PADH;
        int kb = it * BKG;
        constexpr int NLD = 2 + BN / 64;
        #pragma unroll
        for (int i = 0; i < NLD; i++) {
            int idx = tid + i * 256;
            if (idx < 512) {
                int r  = idx >> 2;
                int c8 = (idx & 3) << 3;
                cp_async16(&sa[r * PADH + c8], &A[(size_t)(m0 + r) * lda + kb + c8]);
            } else {
                int j  = idx - 512;
                int r  = j >> 2;
                int c8 = (j & 3) << 3;
                cp_async16(&sb[r * PADH + c8], &W[(size_t)(j0 + r) * K + kb + c8]);
            }
        }
    };

    wmma::fragment<wmma::accumulator, 16, 16, 16, float> c[2][NF];
    #pragma unroll
    for (int i = 0; i < 2; i++)
        #pragma unroll
        for (int j = 0; j < NF; j++)
            wmma::fill_fragment(c[i][j], 0.0f);

    #pragma unroll
    for (int s = 0; s < NST - 1; s++) {
        if (s < niters) issue_load(s, s);
        cp_commit();
    }

    for (int it = 0; it < niters; it++) {
        if (it + NST - 1 < niters) issue_load(it + NST - 1, (it + NST - 1) % NST);
        cp_commit();
        cp_wait<NST - 1>();
        __syncthreads();

        __half* sa = smem_all + (it % NST) * STG;
        __half* sb = sa + BM * PADH;

        #pragma unroll
        for (int kk = 0; kk < BKG; kk += 16) {
            wmma::fragment<wmma::matrix_a, 16, 16, 16, __half, wmma::row_major> af[2];
            wmma::fragment<wmma::matrix_b, 16, 16, 16, __half, wmma::col_major> bf[NF];
            #pragma unroll
            for (int mf = 0; mf < 2; mf++)
                wmma::load_matrix_sync(af[mf], &sa[(wm + mf * 16) * PADH + kk], PADH);
            #pragma unroll
            for (int nf = 0; nf < NF; nf++)
                wmma::load_matrix_sync(bf[nf], &sb[(wn + nf * 16) * PADH + kk], PADH);
            #pragma unroll
            for (int mf = 0; mf < 2; mf++)
                #pragma unroll
                for (int nf = 0; nf < NF; nf++)
                    wmma::mma_sync(c[mf][nf], af[mf], bf[nf], c[mf][nf]);
        }
        __syncthreads();
    }

    // Epilogue. Thread quad geometry: rows r = (lane>>2)+8i, col c4=(lane&3)*4.
    const int c4 = (lane & 3) << 2;
    const int bb = m0 >> 12;                 // batch (NN=4096, BM=128 divides)
    const int chA = ((m0 & (NN - 1)) + wm) >> 4;   // first chunk of warp tile
    float* stage = reinterpret_cast<float*>(smem_all) + warp * (32 * 20);

    #pragma unroll
    for (int nf = 0; nf < NF; nf++) {
        wmma::store_matrix_sync(stage,           c[0][nf], 20, wmma::mem_row_major);
        wmma::store_matrix_sync(stage + 16 * 20, c[1][nf], 20, wmma::mem_row_major);
        __syncwarp();
        float vv4[4][4];
        #pragma unroll
        for (int i = 0; i < 4; i++) {
            int r = (lane >> 2) + 8 * i;     // 0..31
            float4 v = *reinterpret_cast<float4*>(&stage[r * 20 + c4]);
            float* vv = vv4[i];
            vv[0] = v.x; vv[1] = v.y; vv[2] = v.z; vv[3] = v.w;
            #pragma unroll
            for (int t = 0; t < 4; t++)
                vv[t] += bias[j0 + wn + nf * 16 + c4 + t];
            if (op == 1) {
                #pragma unroll
                for (int t = 0; t < 4; t++) vv[t] = sigmoid_f(vv[t]);
            } else if (op == 2) {
                float e0 = gelu_exact(vv[0]), e1 = gelu_exact(vv[1]);
                float e2 = gelu_exact(vv[2]), e3 = gelu_exact(vv[3]);
                vv[0] = e0; vv[1] = e0 * e1;   // (lo, lo*hi) pairs
                vv[2] = e2; vv[3] = e2 * e3;
            }
            OutT* dst = &out[(size_t)(m0 + wm + r) * ldo + j0 + wn + nf * 16 + c4];
            if (sizeof(OutT) == 2) {
                __half2 h0 = __floats2half2_rn(vv[0], vv[1]);
                __half2 h1 = __floats2half2_rn(vv[2], vv[3]);
                uint2 u;
                u.x = *reinterpret_cast<unsigned*>(&h0);
                u.y = *reinterpret_cast<unsigned*>(&h1);
                *reinterpret_cast<uint2*>(dst) = u;
            } else {
                *reinterpret_cast<float4*>(dst) = make_float4(vv[0], vv[1], vv[2], vv[3]);
            }
        }
        if (op == 2) {
            // Per-chunk column sums: chunkA = rows i=0,1; chunkB = rows i=2,3.
            float sA[4], sB[4];
            #pragma unroll
            for (int t = 0; t < 4; t++) {
                sA[t] = vv4[0][t] + vv4[1][t];
                sB[t] = vv4[2][t] + vv4[3][t];
            }
            #pragma unroll
            for (int mk = 4; mk <= 16; mk <<= 1) {
                #pragma unroll
                for (int t = 0; t < 4; t++) {
                    sA[t] += __shfl_xor_sync(0xFFFFFFFFu, sA[t], mk);
                    sB[t] += __shfl_xor_sync(0xFFFFFFFFu, sB[t], mk);
                }
            }
            if ((lane >> 2) == 0) {          // lanes 0..3 hold full 16-row sums
                int p0 = (j0 - 512) + wn + nf * 16 + c4;
                #pragma unroll
                for (int t = 0; t < 4; t++) {
                    size_t gp = ((size_t)bb * DE + p0 + t) * NCHUNK;
                    g_part[gp + chA]     = sA[t];
                    g_part[gp + chA + 1] = sB[t];
                }
            }
        }
        __syncwarp();
    }
}

// ---------------------------------------------------------------------------
// Exclusive scan along c for each (b,p): one warp per (b,p), coalesced.
// All 8 segment loads hoisted (independent) -> MLP 8; serial carry only.
// ---------------------------------------------------------------------------
__global__ __launch_bounds__(256) void scan_part_kernel() {
    const int w    = (blockIdx.x * 256 + threadIdx.x) >> 5;  // 0..2047 = (b,p)
    const int lane = threadIdx.x & 31;
    size_t base = (size_t)w * NCHUNK;

    float v[8];
    #pragma unroll
    for (int seg = 0; seg < 8; seg++)
        v[seg] = g_part[base + seg * 32 + lane];

    float carry = 0.0f;
    #pragma unroll
    for (int seg = 0; seg < 8; seg++) {
        float x = v[seg];
        #pragma unroll
        for (int off = 1; off < 32; off <<= 1) {
            float y = __shfl_up_sync(0xFFFFFFFFu, x, off);
            if (lane >= off) x += y;
        }
        g_part[base + seg * 32 + lane] = carry + x - v[seg];   // exclusive
        carry += __shfl_sync(0xFFFFFFFFu, x, 31);
    }
}

// ---------------------------------------------------------------------------
// Pass B: 512 threads, 4 row-groups of 4 rows. Thread d owns channels 4d..4d+3.
// Each group builds a 4-row register prefix; cross-group offsets via smem
// totals (<=3 adds). Writes fp16 g_o_h (permuted order, linear addressing).
// ---------------------------------------------------------------------------
__global__ __launch_bounds__(512) void scan_apply_kernel() {
    const int b   = blockIdx.x / NCHUNK;
    const int ch  = blockIdx.x % NCHUNK;
    const int d   = threadIdx.x & 127;   // channel group: p = 4d..4d+3
    const int grp = threadIdx.x >> 7;    // 0..3, rows grp*4 .. grp*4+3

    // Offsets (exclusive chunk prefix), 4 scalar loads, issued early.
    size_t pb = ((size_t)b * DE + 4 * d) * NCHUNK + ch;
    float4 off;
    off.x = g_part[pb];
    off.y = g_part[pb + NCHUNK];
    off.z = g_part[pb + 2 * (size_t)NCHUNK];
    off.w = g_part[pb + 3 * (size_t)NCHUNK];

    size_t rowbase = ((size_t)(b * NN + ch * CHUNK + grp * 4)) * 1024;
    float4 cum[4];
    float4 run = {0.f, 0.f, 0.f, 0.f};
    #pragma unroll
    for (int r = 0; r < 4; r++) {
        uint2 u = *reinterpret_cast<const uint2*>(&g_sh_h[rowbase + (size_t)r * 1024 + 512 + 4 * d]);
        float2 f0 = __half22float2(*reinterpret_cast<__half2*>(&u.x));
        float2 f1 = __half22float2(*reinterpret_cast<__half2*>(&u.y));
        run.x += f0.x; run.y += f0.y; run.z += f1.x; run.w += f1.y;
        cum[r] = run;
    }

    __shared__ float4 s_tot[4][128];
    s_tot[grp][d] = run;
    __syncthreads();
    #pragma unroll
    for (int g = 0; g < 3; g++) {
        if (g < grp) {
            float4 t = s_tot[g][d];
            off.x += t.x; off.y += t.y; off.z += t.z; off.w += t.w;
        }
    }

    #pragma unroll
    for (int r = 0; r < 4; r++) {
        int n = ch * CHUNK + grp * 4 + r;
        size_t row = (size_t)(b * NN + n);
        float rec = 1.0f / ((float)(n + 1) + 1e-7f);
        uint2 ug = *reinterpret_cast<const uint2*>(&g_sh_h[row * 1024 + 4 * d]);
        float2 G0 = __half22float2(*reinterpret_cast<__half2*>(&ug.x));
        float2 G1 = __half22float2(*reinterpret_cast<__half2*>(&ug.y));
        float o0 = G0.x * (off.x + cum[r].x) * rec;
        float o1 = G0.y * (off.y + cum[r].y) * rec;
        float o2 = G1.x * (off.z + cum[r].z) * rec;
        float o3 = G1.y * (off.w + cum[r].w) * rec;
        __half2 h0 = __floats2half2_rn(o0, o1);
        __half2 h1 = __floats2half2_rn(o2, o3);
        uint2 uo;
        uo.x = *reinterpret_cast<unsigned*>(&h0);
        uo.y = *reinterpret_cast<unsigned*>(&h1);
        *reinterpret_cast<uint2*>(&g_o_h[row * DE + 4 * d]) = uo;
    }
}

// ---------------------------------------------------------------------------
// Launcher
// ---------------------------------------------------------------------------
extern "C" void kernel_launch(void* const* d_in, const int* in_sizes, int n_in,
                              void* d_out, int out_size) {
    const float* xq   = (const float*)d_in[0];
    const float* W_se = (const float*)d_in[2];
    const float* b_se = (const float*)d_in[3];
    const float* W_po = (const float*)d_in[4];
    const float* b_po = (const float*)d_in[5];
    const float* W_ag = (const float*)d_in[6];
    const float* b_ag = (const float*)d_in[7];
    float* out = (float*)d_out;

    __half* shh_ptr = nullptr;
    __half* oh_ptr  = nullptr;
    __half* xqh_ptr = nullptr;
    __half* w1_ptr  = nullptr;
    __half* w3_ptr  = nullptr;
    float*  b1_ptr  = nullptr;
    cudaGetSymbolAddress((void**)&shh_ptr, g_sh_h);
    cudaGetSymbolAddress((void**)&oh_ptr,  g_o_h);
    cudaGetSymbolAddress((void**)&xqh_ptr, g_xq_h);
    cudaGetSymbolAddress((void**)&w1_ptr,  g_w1_h);
    cudaGetSymbolAddress((void**)&w3_ptr,  g_w3_h);
    cudaGetSymbolAddress((void**)&b1_ptr,  g_b1);

    // fp16 conversions + channel permutation (one launch)
    conv_all_kernel<<<(TOT * DIMV) / 1024, 256>>>(xq, W_se, W_po, W_ag, b_se, b_po);

    // GEMM1+2 fused: gate | combined-gelu (fp16, permuted), + chunk sums
    {
        dim3 grid(TOT / BM, 1024 / 128);   // (128, 8)
        gemm_f16_kernel<128, 2, __half><<<grid, 256>>>(
            xqh_ptr, DIMV,
            w1_ptr, b1_ptr,
            /*op0=*/1, /*op1=*/2, /*opSplit=*/DE, /*K=*/DIMV,
            shh_ptr, /*ldo=*/1024);
    }

    scan_part_kernel<<<(BB * DE * 32) / 256, 256>>>();   // 256 blocks, warp/(b,p)
    scan_apply_kernel<<<BB * NCHUNK, 512>>>();

    // GEMM3: [16384,512] x [128,512]^T -> out (fp32); W_ag K-dim permuted
    {
        dim3 grid(TOT / BM, DIMV / 64);    // (128, 2)
        gemm_f16_kernel<64, 3, float><<<grid, 256>>>(
            oh_ptr, DE,
            w3_ptr, b_ag,
            /*op0=*/0, /*op1=*/0, /*opSplit=*/1 << 30, /*K=*/DE,
            out, /*ldo=*/DIMV);
    }
}

// round 15
// speedup vs baseline: 1.0234x; 1.0234x over previous
#include <cuda_runtime.h>
#include <cuda_fp16.h>
#include <mma.h>
#include <cstdint>

using namespace nvcuda;

#define BB 4
#define NN 4096
#define DIMV 128
#define DE 512
#define TOT (BB * NN)          // 16384 rows
#define CHUNK 8
#define NCHUNK (NN / CHUNK)    // 512

// Scratch (allocation-free: __device__ globals)
// Channel permutation: p=2d <-> orig d (lo), p=2d+1 <-> orig d+256 (hi).
// g_sh_h per row (fp16): [0,512) = sigmoid(s) gate (perm), [512,1024) = combined
//   where combined[2d] = gelu(h_d), combined[2d+1] = gelu(h_d)*gelu(h_{d+256}).
__device__ __half g_sh_h[(size_t)TOT * 1024];
__device__ __half g_o_h[(size_t)TOT * DE];    // gated aggregation (fp16, perm order)
// g_part layout: [b][p][c]  (p-major; c contiguous), 8-row chunks
__device__ float  g_part[BB * DE * NCHUNK];
__device__ __half g_xq_h[(size_t)TOT * DIMV]; // fp16 copy of xq
__device__ __half g_w1_h[1024 * DIMV];        // [W_se; W_po] fp16, rows permuted
__device__ __half g_w3_h[DIMV * DE];          // W_ag fp16, K-dim permuted
__device__ float  g_b1[1024];                 // [b_se; b_po] permuted

#define BM 128
#define BKG 32
#define PADH 40                 // half pitch: 80 B, multiple of 16

__device__ __forceinline__ float gelu_exact(float x) {
    return 0.5f * x * (1.0f + erff(x * 0.70710678118654752f));
}
__device__ __forceinline__ float sigmoid_f(float x) {
    return 1.0f / (1.0f + expf(-x));
}
__device__ __forceinline__ int perm_orig(int p) {     // permuted -> original channel
    return (p & 1) ? 256 + (p >> 1) : (p >> 1);
}

__device__ __forceinline__ void cp_async16(void* smem_dst, const void* gmem_src) {
    unsigned s = (unsigned)__cvta_generic_to_shared(smem_dst);
    asm volatile("cp.async.cg.shared.global [%0], [%1], 16;" :: "r"(s), "l"(gmem_src));
}
__device__ __forceinline__ void cp_commit() {
    asm volatile("cp.async.commit_group;");
}
template <int N>
__device__ __forceinline__ void cp_wait() {
    asm volatile("cp.async.wait_group %0;" :: "n"(N));
}

// ---------------------------------------------------------------------------
// Merged conversion kernel (one launch) — applies the channel permutation.
// ---------------------------------------------------------------------------
__global__ __launch_bounds__(256) void conv_all_kernel(
    const float* __restrict__ x,
    const float* __restrict__ wse, const float* __restrict__ wpo,
    const float* __restrict__ wag,
    const float* __restrict__ bse, const float* __restrict__ bpo)
{
    int i = blockIdx.x * 256 + threadIdx.x;    // grid: 2048*256 = 524288
    {   // xq: 2,097,152 elems = 524,288 float4 slots
        int e = i * 4;
        float4 v = *reinterpret_cast<const float4*>(&x[e]);
        *reinterpret_cast<__half2*>(&g_xq_h[e])     = __floats2half2_rn(v.x, v.y);
        *reinterpret_cast<__half2*>(&g_xq_h[e + 2]) = __floats2half2_rn(v.z, v.w);
    }
    if (i < 65536) {
        {   // W_se / W_po: permuted rows. i = r*128 + k
            int r = i >> 7, k = i & 127;
            int po = perm_orig(r);
            g_w1_h[i]         = __float2half(wse[po * 128 + k]);
            g_w1_h[65536 + i] = __float2half(wpo[po * 128 + k]);
        }
        {   // W_ag: permuted K. i = j*512 + p
            int j = i >> 9, p = i & 511;
            g_w3_h[i] = __float2half(wag[j * 512 + perm_orig(p)]);
        }
        if (i < 512) {
            int po = perm_orig(i);
            g_b1[i] = bse[po]; g_b1[512 + i] = bpo[po];
        }
    }
}

// ---------------------------------------------------------------------------
// fp16 wmma GEMM (fp32 accum), BM=128 x BN tile, BK=32, NST-stage cp.async.
// 256 threads = 8 warps (4 M x 2 N); warp tile 32 x (BN/2).
// op: 0=none 1=sigmoid 2=gelu+pair-combine (+ fused per-8-row-chunk column
//     sums into g_part — each (chunk,p) owned by exactly one warp).
// ---------------------------------------------------------------------------
template <int BN, int NST, typename OutT>
__global__ __launch_bounds__(256) void gemm_f16_kernel(
    const __half* __restrict__ A, int lda,
    const __half* __restrict__ W, const float* __restrict__ bias,
    int op0, int op1, int opSplit, int K,
    OutT* __restrict__ out, int ldo)
{
    constexpr int NF  = BN / 32;
    constexpr int STG = (BM + BN) * PADH;
    __shared__ __half smem_all[NST * STG];

    const int m0 = blockIdx.x * BM;
    const int j0 = blockIdx.y * BN;
    const int op = (j0 < opSplit) ? op0 : op1;

    const int tid  = threadIdx.x;
    const int warp = tid >> 5;
    const int lane = tid & 31;
    const int wm = (warp & 3) * 32;
    const int wn = (warp >> 2) * (BN / 2);

    const int niters = K / BKG;

    auto issue_load = [&](int it, int buf) {
        __half* sa = smem_all + buf * STG;
        __half* sb = sa + BM * PADH;
        int kb = it * BKG;
        constexpr int NLD = 2 + BN / 64;
        #pragma unroll
        for (int i = 0; i < NLD; i++) {
            int idx = tid + i * 256;
            if (idx < 512) {
                int r  = idx >> 2;
                int c8 = (idx & 3) << 3;
                cp_async16(&sa[r * PADH + c8], &A[(size_t)(m0 + r) * lda + kb + c8]);
            } else {
                int j  = idx - 512;
                int r  = j >> 2;
                int c8 = (j & 3) << 3;
                cp_async16(&sb[r * PADH + c8], &W[(size_t)(j0 + r) * K + kb + c8]);
            }
        }
    };

    wmma::fragment<wmma::accumulator, 16, 16, 16, float> c[2][NF];
    #pragma unroll
    for (int i = 0; i < 2; i++)
        #pragma unroll
        for (int j = 0; j < NF; j++)
            wmma::fill_fragment(c[i][j], 0.0f);

    #pragma unroll
    for (int s = 0; s < NST - 1; s++) {
        if (s < niters) issue_load(s, s);
        cp_commit();
    }

    for (int it = 0; it < niters; it++) {
        if (it + NST - 1 < niters) issue_load(it + NST - 1, (it + NST - 1) % NST);
        cp_commit();
        cp_wait<NST - 1>();
        __syncthreads();

        __half* sa = smem_all + (it % NST) * STG;
        __half* sb = sa + BM * PADH;

        #pragma unroll
        for (int kk = 0; kk < BKG; kk += 16) {
            wmma::fragment<wmma::matrix_a, 16, 16, 16, __half, wmma::row_major> af[2];
            wmma::fragment<wmma::matrix_b, 16, 16, 16, __half, wmma::col_major> bf[NF];
            #pragma unroll
            for (int mf = 0; mf < 2; mf++)
                wmma::load_matrix_sync(af[mf], &sa[(wm + mf * 16) * PADH + kk], PADH);
            #pragma unroll
            for (int nf = 0; nf < NF; nf++)
                wmma::load_matrix_sync(bf[nf], &sb[(wn + nf * 16) * PADH + kk], PADH);
            #pragma unroll
            for (int mf = 0; mf < 2; mf++)
                #pragma unroll
                for (int nf = 0; nf < NF; nf++)
                    wmma::mma_sync(c[mf][nf], af[mf], bf[nf], c[mf][nf]);
        }
        __syncthreads();
    }

    // Epilogue. Thread quad geometry: rows r = (lane>>2)+8i, col c4=(lane&3)*4.
    // Row group i (8 rows) == 8-row chunk (chA + i).
    const int c4 = (lane & 3) << 2;
    const int bb = m0 >> 12;                        // batch
    const int chA = ((m0 & (NN - 1)) + wm) >> 3;    // first 8-row chunk of warp tile
    float* stage = reinterpret_cast<float*>(smem_all) + warp * (32 * 20);

    #pragma unroll
    for (int nf = 0; nf < NF; nf++) {
        wmma::store_matrix_sync(stage,           c[0][nf], 20, wmma::mem_row_major);
        wmma::store_matrix_sync(stage + 16 * 20, c[1][nf], 20, wmma::mem_row_major);
        __syncwarp();
        float vv4[4][4];
        #pragma unroll
        for (int i = 0; i < 4; i++) {
            int r = (lane >> 2) + 8 * i;     // 0..31
            float4 v = *reinterpret_cast<float4*>(&stage[r * 20 + c4]);
            float* vv = vv4[i];
            vv[0] = v.x; vv[1] = v.y; vv[2] = v.z; vv[3] = v.w;
            #pragma unroll
            for (int t = 0; t < 4; t++)
                vv[t] += bias[j0 + wn + nf * 16 + c4 + t];
            if (op == 1) {
                #pragma unroll
                for (int t = 0; t < 4; t++) vv[t] = sigmoid_f(vv[t]);
            } else if (op == 2) {
                float e0 = gelu_exact(vv[0]), e1 = gelu_exact(vv[1]);
                float e2 = gelu_exact(vv[2]), e3 = gelu_exact(vv[3]);
                vv[0] = e0; vv[1] = e0 * e1;   // (lo, lo*hi) pairs
                vv[2] = e2; vv[3] = e2 * e3;
            }
            OutT* dst = &out[(size_t)(m0 + wm + r) * ldo + j0 + wn + nf * 16 + c4];
            if (sizeof(OutT) == 2) {
                __half2 h0 = __floats2half2_rn(vv[0], vv[1]);
                __half2 h1 = __floats2half2_rn(vv[2], vv[3]);
                uint2 u;
                u.x = *reinterpret_cast<unsigned*>(&h0);
                u.y = *reinterpret_cast<unsigned*>(&h1);
                *reinterpret_cast<uint2*>(dst) = u;
            } else {
                *reinterpret_cast<float4*>(dst) = make_float4(vv[0], vv[1], vv[2], vv[3]);
            }
        }
        if (op == 2) {
            // Per-8-row-chunk column sums: row group i = chunk chA+i.
            float s[4][4];
            #pragma unroll
            for (int i = 0; i < 4; i++)
                #pragma unroll
                for (int t = 0; t < 4; t++)
                    s[i][t] = vv4[i][t];
            #pragma unroll
            for (int mk = 4; mk <= 16; mk <<= 1)
                #pragma unroll
                for (int i = 0; i < 4; i++)
                    #pragma unroll
                    for (int t = 0; t < 4; t++)
                        s[i][t] += __shfl_xor_sync(0xFFFFFFFFu, s[i][t], mk);
            if ((lane >> 2) == 0) {          // lanes 0..3 hold full 8-row sums
                int p0 = (j0 - 512) + wn + nf * 16 + c4;
                #pragma unroll
                for (int t = 0; t < 4; t++) {
                    size_t gp = ((size_t)bb * DE + p0 + t) * NCHUNK;
                    #pragma unroll
                    for (int i = 0; i < 4; i++)
                        g_part[gp + chA + i] = s[i][t];
                }
            }
        }
        __syncwarp();
    }
}

// ---------------------------------------------------------------------------
// Exclusive scan along c for each (b,p): one warp per (b,p), coalesced.
// 16 segments of 32; all loads hoisted (independent), serial carry only.
// ---------------------------------------------------------------------------
__global__ __launch_bounds__(256) void scan_part_kernel() {
    const int w    = (blockIdx.x * 256 + threadIdx.x) >> 5;  // 0..2047 = (b,p)
    const int lane = threadIdx.x & 31;
    size_t base = (size_t)w * NCHUNK;

    float v[16];
    #pragma unroll
    for (int seg = 0; seg < 16; seg++)
        v[seg] = g_part[base + seg * 32 + lane];

    float carry = 0.0f;
    #pragma unroll
    for (int seg = 0; seg < 16; seg++) {
        float x = v[seg];
        #pragma unroll
        for (int off = 1; off < 32; off <<= 1) {
            float y = __shfl_up_sync(0xFFFFFFFFu, x, off);
            if (lane >= off) x += y;
        }
        g_part[base + seg * 32 + lane] = carry + x - v[seg];   // exclusive
        carry += __shfl_sync(0xFFFFFFFFu, x, 31);
    }
}

// ---------------------------------------------------------------------------
// Pass B: SINGLE-PASS apply. Block = 16 rows = 2 chunks of 8; 256 threads.
// grp = tid>>7 selects the chunk; thread d=tid&127 owns channels 4d..4d+3.
// Offsets come directly from g_part (8-row granularity) -> no smem, no sync,
// no prefix buffering: walk 8 rows accumulating run on the fly.
// ---------------------------------------------------------------------------
__global__ __launch_bounds__(256) void scan_apply_kernel() {
    const int blk = blockIdx.x;            // 0..1023
    const int b   = blk >> 8;              // / 256 segments
    const int seg = blk & 255;             // 16-row segment
    const int d   = threadIdx.x & 127;     // channels p = 4d..4d+3
    const int grp = threadIdx.x >> 7;      // chunk within segment
    const int ch  = seg * 2 + grp;         // global 8-row chunk

    // Exclusive chunk offsets (4 scalar loads, issued early).
    size_t pb = ((size_t)b * DE + 4 * d) * NCHUNK + ch;
    float4 off;
    off.x = g_part[pb];
    off.y = g_part[pb + NCHUNK];
    off.z = g_part[pb + 2 * (size_t)NCHUNK];
    off.w = g_part[pb + 3 * (size_t)NCHUNK];

    const int n0 = ch * CHUNK;
    size_t rowbase = ((size_t)(b * NN + n0)) * 1024;
    float4 run = {0.f, 0.f, 0.f, 0.f};
    #pragma unroll
    for (int r = 0; r < 8; r++) {
        size_t ro = rowbase + (size_t)r * 1024;
        uint2 u  = *reinterpret_cast<const uint2*>(&g_sh_h[ro + 512 + 4 * d]);
        uint2 ug = *reinterpret_cast<const uint2*>(&g_sh_h[ro + 4 * d]);
        float2 f0 = __half22float2(*reinterpret_cast<__half2*>(&u.x));
        float2 f1 = __half22float2(*reinterpret_cast<__half2*>(&u.y));
        run.x += f0.x; run.y += f0.y; run.z += f1.x; run.w += f1.y;

        float rec = 1.0f / ((float)(n0 + r + 1) + 1e-7f);
        float2 G0 = __half22float2(*reinterpret_cast<__half2*>(&ug.x));
        float2 G1 = __half22float2(*reinterpret_cast<__half2*>(&ug.y));
        float o0 = G0.x * (off.x + run.x) * rec;
        float o1 = G0.y * (off.y + run.y) * rec;
        float o2 = G1.x * (off.z + run.z) * rec;
        float o3 = G1.y * (off.w + run.w) * rec;
        __half2 h0 = __floats2half2_rn(o0, o1);
        __half2 h1 = __floats2half2_rn(o2, o3);
        uint2 uo;
        uo.x = *reinterpret_cast<unsigned*>(&h0);
        uo.y = *reinterpret_cast<unsigned*>(&h1);
        *reinterpret_cast<uint2*>(&g_o_h[(size_t)(b * NN + n0 + r) * DE + 4 * d]) = uo;
    }
}

// ---------------------------------------------------------------------------
// Launcher
// ---------------------------------------------------------------------------
extern "C" void kernel_launch(void* const* d_in, const int* in_sizes, int n_in,
                              void* d_out, int out_size) {
    const float* xq   = (const float*)d_in[0];
    const float* W_se = (const float*)d_in[2];
    const float* b_se = (const float*)d_in[3];
    const float* W_po = (const float*)d_in[4];
    const float* b_po = (const float*)d_in[5];
    const float* W_ag = (const float*)d_in[6];
    const float* b_ag = (const float*)d_in[7];
    float* out = (float*)d_out;

    __half* shh_ptr = nullptr;
    __half* oh_ptr  = nullptr;
    __half* xqh_ptr = nullptr;
    __half* w1_ptr  = nullptr;
    __half* w3_ptr  = nullptr;
    float*  b1_ptr  = nullptr;
    cudaGetSymbolAddress((void**)&shh_ptr, g_sh_h);
    cudaGetSymbolAddress((void**)&oh_ptr,  g_o_h);
    cudaGetSymbolAddress((void**)&xqh_ptr, g_xq_h);
    cudaGetSymbolAddress((void**)&w1_ptr,  g_w1_h);
    cudaGetSymbolAddress((void**)&w3_ptr,  g_w3_h);
    cudaGetSymbolAddress((void**)&b1_ptr,  g_b1);

    // fp16 conversions + channel permutation (one launch)
    conv_all_kernel<<<(TOT * DIMV) / 1024, 256>>>(xq, W_se, W_po, W_ag, b_se, b_po);

    // GEMM1+2 fused: gate | combined-gelu (fp16, permuted), + 8-row chunk sums
    {
        dim3 grid(TOT / BM, 1024 / 128);   // (128, 8)
        gemm_f16_kernel<128, 2, __half><<<grid, 256>>>(
            xqh_ptr, DIMV,
            w1_ptr, b1_ptr,
            /*op0=*/1, /*op1=*/2, /*opSplit=*/DE, /*K=*/DIMV,
            shh_ptr, /*ldo=*/1024);
    }

    scan_part_kernel<<<(BB * DE * 32) / 256, 256>>>();   // 256 blocks, warp/(b,p)
    scan_apply_kernel<<<BB * (NN / 16), 256>>>();        // 1024 blocks, single-pass

    // GEMM3: [16384,512] x [128,512]^T -> out (fp32); W_ag K-dim permuted
    {
        dim3 grid(TOT / BM, DIMV / 64);    // (128, 2)
        gemm_f16_kernel<64, 3, float><<<grid, 256>>>(
            oh_ptr, DE,
            w3_ptr, b_ag,
            /*op0=*/0, /*op1=*/0, /*opSplit=*/1 << 30, /*K=*/DE,
            out, /*ldo=*/DIMV);
    }
}

// round 16
// speedup vs baseline: 1.0281x; 1.0046x over previous
#include <cuda_runtime.h>
#include <cuda_fp16.h>
#include <mma.h>
#include <cstdint>

using namespace nvcuda;

#define BB 4
#define NN 4096
#define DIMV 128
#define DE 512
#define TOT (BB * NN)          // 16384 rows
#define CHUNK 8
#define NCHUNK (NN / CHUNK)    // 512

// Scratch (allocation-free: __device__ globals)
// Channel permutation: p=2d <-> orig d (lo), p=2d+1 <-> orig d+256 (hi).
// g_sh_h per row (fp16): [0,512) = sigmoid(s) gate (perm), [512,1024) = combined
//   where combined[2d] = gelu(h_d), combined[2d+1] = gelu(h_d)*gelu(h_{d+256}).
__device__ __half g_sh_h[(size_t)TOT * 1024];
__device__ __half g_o_h[(size_t)TOT * DE];    // gated aggregation (fp16, perm order)
// g_part layout: [b][p][c]  (p-major; c contiguous), 8-row chunks
__device__ float  g_part[BB * DE * NCHUNK];
__device__ __half g_xq_h[(size_t)TOT * DIMV]; // fp16 copy of xq
__device__ __half g_w1_h[1024 * DIMV];        // [W_se; W_po] fp16, rows permuted
__device__ __half g_w3_h[DIMV * DE];          // W_ag fp16, K-dim permuted
__device__ float  g_b1[1024];                 // [b_se; b_po] permuted

#define BM 128
#define BKG 32
#define PADH 40                 // half pitch: 80 B, multiple of 16

__device__ __forceinline__ float gelu_exact(float x) {
    return 0.5f * x * (1.0f + erff(x * 0.70710678118654752f));
}
__device__ __forceinline__ float sigmoid_f(float x) {
    return 1.0f / (1.0f + expf(-x));
}
__device__ __forceinline__ int perm_orig(int p) {     // permuted -> original channel
    return (p & 1) ? 256 + (p >> 1) : (p >> 1);
}

__device__ __forceinline__ void cp_async16(void* smem_dst, const void* gmem_src) {
    unsigned s = (unsigned)__cvta_generic_to_shared(smem_dst);
    asm volatile("cp.async.cg.shared.global [%0], [%1], 16;" :: "r"(s), "l"(gmem_src));
}
__device__ __forceinline__ void cp_commit() {
    asm volatile("cp.async.commit_group;");
}
template <int N>
__device__ __forceinline__ void cp_wait() {
    asm volatile("cp.async.wait_group %0;" :: "n"(N));
}

// ---------------------------------------------------------------------------
// Merged conversion kernel (one launch) — applies the channel permutation.
// ---------------------------------------------------------------------------
__global__ __launch_bounds__(256) void conv_all_kernel(
    const float* __restrict__ x,
    const float* __restrict__ wse, const float* __restrict__ wpo,
    const float* __restrict__ wag,
    const float* __restrict__ bse, const float* __restrict__ bpo)
{
    int i = blockIdx.x * 256 + threadIdx.x;    // grid: 2048*256 = 524288
    {   // xq: 2,097,152 elems = 524,288 float4 slots
        int e = i * 4;
        float4 v = *reinterpret_cast<const float4*>(&x[e]);
        *reinterpret_cast<__half2*>(&g_xq_h[e])     = __floats2half2_rn(v.x, v.y);
        *reinterpret_cast<__half2*>(&g_xq_h[e + 2]) = __floats2half2_rn(v.z, v.w);
    }
    if (i < 65536) {
        {   // W_se / W_po: permuted rows. i = r*128 + k
            int r = i >> 7, k = i & 127;
            int po = perm_orig(r);
            g_w1_h[i]         = __float2half(wse[po * 128 + k]);
            g_w1_h[65536 + i] = __float2half(wpo[po * 128 + k]);
        }
        {   // W_ag: permuted K. i = j*512 + p
            int j = i >> 9, p = i & 511;
            g_w3_h[i] = __float2half(wag[j * 512 + perm_orig(p)]);
        }
        if (i < 512) {
            int po = perm_orig(i);
            g_b1[i] = bse[po]; g_b1[512 + i] = bpo[po];
        }
    }
}

// ---------------------------------------------------------------------------
// fp16 wmma GEMM (fp32 accum), BM=128 x BN tile, BK=32, NST-stage cp.async.
// 256 threads = 8 warps (4 M x 2 N); warp tile 32 x (BN/2).
// op: 0=none 1=sigmoid 2=gelu+pair-combine (+ fused per-8-row-chunk column
//     sums into g_part — each (chunk,p) owned by exactly one warp).
// ---------------------------------------------------------------------------
template <int BN, int NST, typename OutT>
__global__ __launch_bounds__(256) void gemm_f16_kernel(
    const __half* __restrict__ A, int lda,
    const __half* __restrict__ W, const float* __restrict__ bias,
    int op0, int op1, int opSplit, int K,
    OutT* __restrict__ out, int ldo)
{
    constexpr int NF  = BN / 32;
    constexpr int STG = (BM + BN) * PADH;
    __shared__ __half smem_all[NST * STG];

    const int m0 = blockIdx.x * BM;
    const int j0 = blockIdx.y * BN;
    const int op = (j0 < opSplit) ? op0 : op1;

    const int tid  = threadIdx.x;
    const int warp = tid >> 5;
    const int lane = tid & 31;
    const int wm = (warp & 3) * 32;
    const int wn = (warp >> 2) * (BN / 2);

    const int niters = K / BKG;

    auto issue_load = [&](int it, int buf) {
        __half* sa = smem_all + buf * STG;
        __half* sb = sa + BM * PADH;
        int kb = it * BKG;
        constexpr int NLD = 2 + BN / 64;
        #pragma unroll
        for (int i = 0; i < NLD; i++) {
            int idx = tid + i * 256;
            if (idx < 512) {
                int r  = idx >> 2;
                int c8 = (idx & 3) << 3;
                cp_async16(&sa[r * PADH + c8], &A[(size_t)(m0 + r) * lda + kb + c8]);
            } else {
                int j  = idx - 512;
                int r  = j >> 2;
                int c8 = (j & 3) << 3;
                cp_async16(&sb[r * PADH + c8], &W[(size_t)(j0 + r) * K + kb + c8]);
            }
        }
    };

    wmma::fragment<wmma::accumulator, 16, 16, 16, float> c[2][NF];
    #pragma unroll
    for (int i = 0; i < 2; i++)
        #pragma unroll
        for (int j = 0; j < NF; j++)
            wmma::fill_fragment(c[i][j], 0.0f);

    #pragma unroll
    for (int s = 0; s < NST - 1; s++) {
        if (s < niters) issue_load(s, s);
        cp_commit();
    }

    for (int it = 0; it < niters; it++) {
        if (it + NST - 1 < niters) issue_load(it + NST - 1, (it + NST - 1) % NST);
        cp_commit();
        cp_wait<NST - 1>();
        __syncthreads();

        __half* sa = smem_all + (it % NST) * STG;
        __half* sb = sa + BM * PADH;

        #pragma unroll
        for (int kk = 0; kk < BKG; kk += 16) {
            wmma::fragment<wmma::matrix_a, 16, 16, 16, __half, wmma::row_major> af[2];
            wmma::fragment<wmma::matrix_b, 16, 16, 16, __half, wmma::col_major> bf[NF];
            #pragma unroll
            for (int mf = 0; mf < 2; mf++)
                wmma::load_matrix_sync(af[mf], &sa[(wm + mf * 16) * PADH + kk], PADH);
            #pragma unroll
            for (int nf = 0; nf < NF; nf++)
                wmma::load_matrix_sync(bf[nf], &sb[(wn + nf * 16) * PADH + kk], PADH);
            #pragma unroll
            for (int mf = 0; mf < 2; mf++)
                #pragma unroll
                for (int nf = 0; nf < NF; nf++)
                    wmma::mma_sync(c[mf][nf], af[mf], bf[nf], c[mf][nf]);
        }
        __syncthreads();
    }

    // Epilogue. Thread quad geometry: rows r = (lane>>2)+8i, col c4=(lane&3)*4.
    // Row group i (8 rows) == 8-row chunk (chA + i).
    const int c4 = (lane & 3) << 2;
    const int bb = m0 >> 12;                        // batch
    const int chA = ((m0 & (NN - 1)) + wm) >> 3;    // first 8-row chunk of warp tile
    float* stage = reinterpret_cast<float*>(smem_all) + warp * (32 * 20);

    #pragma unroll
    for (int nf = 0; nf < NF; nf++) {
        wmma::store_matrix_sync(stage,           c[0][nf], 20, wmma::mem_row_major);
        wmma::store_matrix_sync(stage + 16 * 20, c[1][nf], 20, wmma::mem_row_major);
        __syncwarp();
        float vv4[4][4];
        #pragma unroll
        for (int i = 0; i < 4; i++) {
            int r = (lane >> 2) + 8 * i;     // 0..31
            float4 v = *reinterpret_cast<float4*>(&stage[r * 20 + c4]);
            float* vv = vv4[i];
            vv[0] = v.x; vv[1] = v.y; vv[2] = v.z; vv[3] = v.w;
            #pragma unroll
            for (int t = 0; t < 4; t++)
                vv[t] += bias[j0 + wn + nf * 16 + c4 + t];
            if (op == 1) {
                #pragma unroll
                for (int t = 0; t < 4; t++) vv[t] = sigmoid_f(vv[t]);
            } else if (op == 2) {
                float e0 = gelu_exact(vv[0]), e1 = gelu_exact(vv[1]);
                float e2 = gelu_exact(vv[2]), e3 = gelu_exact(vv[3]);
                vv[0] = e0; vv[1] = e0 * e1;   // (lo, lo*hi) pairs
                vv[2] = e2; vv[3] = e2 * e3;
            }
            OutT* dst = &out[(size_t)(m0 + wm + r) * ldo + j0 + wn + nf * 16 + c4];
            if (sizeof(OutT) == 2) {
                __half2 h0 = __floats2half2_rn(vv[0], vv[1]);
                __half2 h1 = __floats2half2_rn(vv[2], vv[3]);
                uint2 u;
                u.x = *reinterpret_cast<unsigned*>(&h0);
                u.y = *reinterpret_cast<unsigned*>(&h1);
                *reinterpret_cast<uint2*>(dst) = u;
            } else {
                *reinterpret_cast<float4*>(dst) = make_float4(vv[0], vv[1], vv[2], vv[3]);
            }
        }
        if (op == 2) {
            // Per-8-row-chunk column sums: row group i = chunk chA+i.
            float s[4][4];
            #pragma unroll
            for (int i = 0; i < 4; i++)
                #pragma unroll
                for (int t = 0; t < 4; t++)
                    s[i][t] = vv4[i][t];
            #pragma unroll
            for (int mk = 4; mk <= 16; mk <<= 1)
                #pragma unroll
                for (int i = 0; i < 4; i++)
                    #pragma unroll
                    for (int t = 0; t < 4; t++)
                        s[i][t] += __shfl_xor_sync(0xFFFFFFFFu, s[i][t], mk);
            if ((lane >> 2) == 0) {          // lanes 0..3 hold full 8-row sums
                int p0 = (j0 - 512) + wn + nf * 16 + c4;
                #pragma unroll
                for (int t = 0; t < 4; t++) {
                    size_t gp = ((size_t)bb * DE + p0 + t) * NCHUNK;
                    #pragma unroll
                    for (int i = 0; i < 4; i++)
                        g_part[gp + chA + i] = s[i][t];
                }
            }
        }
        __syncwarp();
    }
}

// ---------------------------------------------------------------------------
// Exclusive scan along c for each (b,p): one warp per (b,p), float4 loads.
// Lane owns 4 consecutive chunks; local 4-scan in regs, warp-scan the 4-sums.
// 4 segments x (5 shuffle steps + bcast) instead of 16 x 6.
// ---------------------------------------------------------------------------
__global__ __launch_bounds__(256) void scan_part_kernel() {
    const int w    = (blockIdx.x * 256 + threadIdx.x) >> 5;  // 0..2047 = (b,p)
    const int lane = threadIdx.x & 31;
    size_t base = (size_t)w * NCHUNK;

    float4 v[4];
    #pragma unroll
    for (int seg = 0; seg < 4; seg++)
        v[seg] = *reinterpret_cast<const float4*>(&g_part[base + seg * 128 + lane * 4]);

    float carry = 0.0f;
    #pragma unroll
    for (int seg = 0; seg < 4; seg++) {
        float t  = v[seg].x + v[seg].y + v[seg].z + v[seg].w;  // local total
        float x  = t;
        #pragma unroll
        for (int off = 1; off < 32; off <<= 1) {
            float y = __shfl_up_sync(0xFFFFFFFFu, x, off);
            if (lane >= off) x += y;
        }
        float base_ex = carry + x - t;      // exclusive prefix of this lane's 4
        float4 o;
        o.x = base_ex;
        o.y = base_ex + v[seg].x;
        o.z = o.y     + v[seg].y;
        o.w = o.z     + v[seg].z;
        *reinterpret_cast<float4*>(&g_part[base + seg * 128 + lane * 4]) = o;
        carry += __shfl_sync(0xFFFFFFFFu, x, 31);
    }
}

// ---------------------------------------------------------------------------
// Pass B: SINGLE-PASS apply, uint4-wide. Block = 32 rows = 4 chunks of 8.
// grp = tid>>6 selects the chunk; thread d=tid&63 owns channels 8d..8d+7.
// No smem, no sync: offsets direct from g_part; walk 8 rows accumulating.
// ---------------------------------------------------------------------------
__global__ __launch_bounds__(256) void scan_apply_kernel() {
    const int blk = blockIdx.x;            // 0..511
    const int b   = blk >> 7;              // / 128 segments
    const int seg = blk & 127;             // 32-row segment
    const int d   = threadIdx.x & 63;      // channels p = 8d..8d+7
    const int grp = threadIdx.x >> 6;      // chunk within segment (0..3)
    const int ch  = seg * 4 + grp;         // global 8-row chunk

    // Exclusive chunk offsets (8 scalar loads, issued early).
    size_t pb = ((size_t)b * DE + 8 * d) * NCHUNK + ch;
    float off[8];
    #pragma unroll
    for (int t = 0; t < 8; t++)
        off[t] = g_part[pb + (size_t)t * NCHUNK];

    const int n0 = ch * CHUNK;
    size_t rowbase = ((size_t)(b * NN + n0)) * 1024;
    float run[8] = {0.f, 0.f, 0.f, 0.f, 0.f, 0.f, 0.f, 0.f};
    #pragma unroll
    for (int r = 0; r < 8; r++) {
        size_t ro = rowbase + (size_t)r * 1024;
        uint4 u  = *reinterpret_cast<const uint4*>(&g_sh_h[ro + 512 + 8 * d]);
        uint4 ug = *reinterpret_cast<const uint4*>(&g_sh_h[ro + 8 * d]);
        float2 f0 = __half22float2(*reinterpret_cast<__half2*>(&u.x));
        float2 f1 = __half22float2(*reinterpret_cast<__half2*>(&u.y));
        float2 f2 = __half22float2(*reinterpret_cast<__half2*>(&u.z));
        float2 f3 = __half22float2(*reinterpret_cast<__half2*>(&u.w));
        run[0] += f0.x; run[1] += f0.y; run[2] += f1.x; run[3] += f1.y;
        run[4] += f2.x; run[5] += f2.y; run[6] += f3.x; run[7] += f3.y;

        float rec = 1.0f / ((float)(n0 + r + 1) + 1e-7f);
        float2 G0 = __half22float2(*reinterpret_cast<__half2*>(&ug.x));
        float2 G1 = __half22float2(*reinterpret_cast<__half2*>(&ug.y));
        float2 G2 = __half22float2(*reinterpret_cast<__half2*>(&ug.z));
        float2 G3 = __half22float2(*reinterpret_cast<__half2*>(&ug.w));
        __half2 h0 = __floats2half2_rn(G0.x * (off[0] + run[0]) * rec,
                                       G0.y * (off[1] + run[1]) * rec);
        __half2 h1 = __floats2half2_rn(G1.x * (off[2] + run[2]) * rec,
                                       G1.y * (off[3] + run[3]) * rec);
        __half2 h2 = __floats2half2_rn(G2.x * (off[4] + run[4]) * rec,
                                       G2.y * (off[5] + run[5]) * rec);
        __half2 h3 = __floats2half2_rn(G3.x * (off[6] + run[6]) * rec,
                                       G3.y * (off[7] + run[7]) * rec);
        uint4 uo;
        uo.x = *reinterpret_cast<unsigned*>(&h0);
        uo.y = *reinterpret_cast<unsigned*>(&h1);
        uo.z = *reinterpret_cast<unsigned*>(&h2);
        uo.w = *reinterpret_cast<unsigned*>(&h3);
        *reinterpret_cast<uint4*>(&g_o_h[(size_t)(b * NN + n0 + r) * DE + 8 * d]) = uo;
    }
}

// ---------------------------------------------------------------------------
// Launcher
// ---------------------------------------------------------------------------
extern "C" void kernel_launch(void* const* d_in, const int* in_sizes, int n_in,
                              void* d_out, int out_size) {
    const float* xq   = (const float*)d_in[0];
    const float* W_se = (const float*)d_in[2];
    const float* b_se = (const float*)d_in[3];
    const float* W_po = (const float*)d_in[4];
    const float* b_po = (const float*)d_in[5];
    const float* W_ag = (const float*)d_in[6];
    const float* b_ag = (const float*)d_in[7];
    float* out = (float*)d_out;

    __half* shh_ptr = nullptr;
    __half* oh_ptr  = nullptr;
    __half* xqh_ptr = nullptr;
    __half* w1_ptr  = nullptr;
    __half* w3_ptr  = nullptr;
    float*  b1_ptr  = nullptr;
    cudaGetSymbolAddress((void**)&shh_ptr, g_sh_h);
    cudaGetSymbolAddress((void**)&oh_ptr,  g_o_h);
    cudaGetSymbolAddress((void**)&xqh_ptr, g_xq_h);
    cudaGetSymbolAddress((void**)&w1_ptr,  g_w1_h);
    cudaGetSymbolAddress((void**)&w3_ptr,  g_w3_h);
    cudaGetSymbolAddress((void**)&b1_ptr,  g_b1);

    // fp16 conversions + channel permutation (one launch)
    conv_all_kernel<<<(TOT * DIMV) / 1024, 256>>>(xq, W_se, W_po, W_ag, b_se, b_po);

    // GEMM1+2 fused: gate | combined-gelu (fp16, permuted), + 8-row chunk sums
    {
        dim3 grid(TOT / BM, 1024 / 128);   // (128, 8)
        gemm_f16_kernel<128, 2, __half><<<grid, 256>>>(
            xqh_ptr, DIMV,
            w1_ptr, b1_ptr,
            /*op0=*/1, /*op1=*/2, /*opSplit=*/DE, /*K=*/DIMV,
            shh_ptr, /*ldo=*/1024);
    }

    scan_part_kernel<<<(BB * DE * 32) / 256, 256>>>();   // 256 blocks, warp/(b,p)
    scan_apply_kernel<<<BB * (NN / 32), 256>>>();        // 512 blocks, single-pass

    // GEMM3: [16384,512] x [128,512]^T -> out (fp32); W_ag K-dim permuted
    {
        dim3 grid(TOT / BM, DIMV / 64);    // (128, 2)
        gemm_f16_kernel<64, 3, float><<<grid, 256>>>(
            oh_ptr, DE,
            w3_ptr, b_ag,
            /*op0=*/0, /*op1=*/0, /*opSplit=*/1 << 30, /*K=*/DE,
            out, /*ldo=*/DIMV);
    }
}

// round 17
// speedup vs baseline: 1.0525x; 1.0236x over previous
#include <cuda_runtime.h>
#include <cuda_fp16.h>
#include <mma.h>
#include <cstdint>

using namespace nvcuda;

#define BB 4
#define NN 4096
#define DIMV 128
#define DE 512
#define TOT (BB * NN)          // 16384 rows
#define CHUNK 8
#define NCHUNK (NN / CHUNK)    // 512

// Scratch (allocation-free: __device__ globals)
// Channel permutation: p=2d <-> orig d (lo), p=2d+1 <-> orig d+256 (hi).
// g_sh_h per row (fp16): [0,512) = sigmoid(s) gate (perm), [512,1024) = combined
//   where combined[2d] = gelu(h_d), combined[2d+1] = gelu(h_d)*gelu(h_{d+256}).
__device__ __half g_sh_h[(size_t)TOT * 1024];
__device__ __half g_o_h[(size_t)TOT * DE];    // gated aggregation (fp16, perm order)
// g_part layout: [b][p][c]  (p-major; c contiguous), 8-row chunks
__device__ float  g_part[BB * DE * NCHUNK];
__device__ __half g_xq_h[(size_t)TOT * DIMV]; // fp16 copy of xq
__device__ __half g_w1_h[1024 * DIMV];        // [W_se; W_po] fp16, rows permuted
__device__ __half g_w3_h[DIMV * DE];          // W_ag fp16, K-dim permuted
__device__ float  g_b1[1024];                 // [b_se; b_po] permuted

#define BM 128
#define BKG 32
#define PADH 40                 // half pitch: 80 B, multiple of 16

__device__ __forceinline__ float gelu_exact(float x) {
    return 0.5f * x * (1.0f + erff(x * 0.70710678118654752f));
}
__device__ __forceinline__ float sigmoid_f(float x) {
    return 1.0f / (1.0f + expf(-x));
}
__device__ __forceinline__ int perm_orig(int p) {     // permuted -> original channel
    return (p & 1) ? 256 + (p >> 1) : (p >> 1);
}

__device__ __forceinline__ void cp_async16(void* smem_dst, const void* gmem_src) {
    unsigned s = (unsigned)__cvta_generic_to_shared(smem_dst);
    asm volatile("cp.async.cg.shared.global [%0], [%1], 16;" :: "r"(s), "l"(gmem_src));
}
__device__ __forceinline__ void cp_commit() {
    asm volatile("cp.async.commit_group;");
}
template <int N>
__device__ __forceinline__ void cp_wait() {
    asm volatile("cp.async.wait_group %0;" :: "n"(N));
}

// ---------------------------------------------------------------------------
// Merged conversion kernel (one launch) — applies the channel permutation.
// ---------------------------------------------------------------------------
__global__ __launch_bounds__(256) void conv_all_kernel(
    const float* __restrict__ x,
    const float* __restrict__ wse, const float* __restrict__ wpo,
    const float* __restrict__ wag,
    const float* __restrict__ bse, const float* __restrict__ bpo)
{
    int i = blockIdx.x * 256 + threadIdx.x;    // grid: 2048*256 = 524288
    {   // xq: 2,097,152 elems = 524,288 float4 slots
        int e = i * 4;
        float4 v = *reinterpret_cast<const float4*>(&x[e]);
        *reinterpret_cast<__half2*>(&g_xq_h[e])     = __floats2half2_rn(v.x, v.y);
        *reinterpret_cast<__half2*>(&g_xq_h[e + 2]) = __floats2half2_rn(v.z, v.w);
    }
    if (i < 65536) {
        {   // W_se / W_po: permuted rows. i = r*128 + k
            int r = i >> 7, k = i & 127;
            int po = perm_orig(r);
            g_w1_h[i]         = __float2half(wse[po * 128 + k]);
            g_w1_h[65536 + i] = __float2half(wpo[po * 128 + k]);
        }
        {   // W_ag: permuted K. i = j*512 + p
            int j = i >> 9, p = i & 511;
            g_w3_h[i] = __float2half(wag[j * 512 + perm_orig(p)]);
        }
        if (i < 512) {
            int po = perm_orig(i);
            g_b1[i] = bse[po]; g_b1[512 + i] = bpo[po];
        }
    }
}

// ---------------------------------------------------------------------------
// fp16 wmma GEMM (fp32 accum), BM=128 x BN tile, BK=32, NST-stage cp.async.
// 256 threads = 8 warps (4 M x 2 N); warp tile 32 x (BN/2).
// op: 0=none 1=sigmoid 2=gelu+pair-combine (+ fused per-8-row-chunk column
//     sums into g_part, float4 stores along the contiguous c axis).
// ---------------------------------------------------------------------------
template <int BN, int NST, typename OutT>
__global__ __launch_bounds__(256) void gemm_f16_kernel(
    const __half* __restrict__ A, int lda,
    const __half* __restrict__ W, const float* __restrict__ bias,
    int op0, int op1, int opSplit, int K,
    OutT* __restrict__ out, int ldo)
{
    constexpr int NF  = BN / 32;
    constexpr int STG = (BM + BN) * PADH;
    __shared__ __half smem_all[NST * STG];

    const int m0 = blockIdx.x * BM;
    const int j0 = blockIdx.y * BN;
    const int op = (j0 < opSplit) ? op0 : op1;

    const int tid  = threadIdx.x;
    const int warp = tid >> 5;
    const int lane = tid & 31;
    const int wm = (warp & 3) * 32;
    const int wn = (warp >> 2) * (BN / 2);

    const int niters = K / BKG;

    auto issue_load = [&](int it, int buf) {
        __half* sa = smem_all + buf * STG;
        __half* sb = sa + BM * PADH;
        int kb = it * BKG;
        constexpr int NLD = 2 + BN / 64;
        #pragma unroll
        for (int i = 0; i < NLD; i++) {
            int idx = tid + i * 256;
            if (idx < 512) {
                int r  = idx >> 2;
                int c8 = (idx & 3) << 3;
                cp_async16(&sa[r * PADH + c8], &A[(size_t)(m0 + r) * lda + kb + c8]);
            } else {
                int j  = idx - 512;
                int r  = j >> 2;
                int c8 = (j & 3) << 3;
                cp_async16(&sb[r * PADH + c8], &W[(size_t)(j0 + r) * K + kb + c8]);
            }
        }
    };

    wmma::fragment<wmma::accumulator, 16, 16, 16, float> c[2][NF];
    #pragma unroll
    for (int i = 0; i < 2; i++)
        #pragma unroll
        for (int j = 0; j < NF; j++)
            wmma::fill_fragment(c[i][j], 0.0f);

    #pragma unroll
    for (int s = 0; s < NST - 1; s++) {
        if (s < niters) issue_load(s, s);
        cp_commit();
    }

    for (int it = 0; it < niters; it++) {
        if (it + NST - 1 < niters) issue_load(it + NST - 1, (it + NST - 1) % NST);
        cp_commit();
        cp_wait<NST - 1>();
        __syncthreads();

        __half* sa = smem_all + (it % NST) * STG;
        __half* sb = sa + BM * PADH;

        #pragma unroll
        for (int kk = 0; kk < BKG; kk += 16) {
            wmma::fragment<wmma::matrix_a, 16, 16, 16, __half, wmma::row_major> af[2];
            wmma::fragment<wmma::matrix_b, 16, 16, 16, __half, wmma::col_major> bf[NF];
            #pragma unroll
            for (int mf = 0; mf < 2; mf++)
                wmma::load_matrix_sync(af[mf], &sa[(wm + mf * 16) * PADH + kk], PADH);
            #pragma unroll
            for (int nf = 0; nf < NF; nf++)
                wmma::load_matrix_sync(bf[nf], &sb[(wn + nf * 16) * PADH + kk], PADH);
            #pragma unroll
            for (int mf = 0; mf < 2; mf++)
                #pragma unroll
                for (int nf = 0; nf < NF; nf++)
                    wmma::mma_sync(c[mf][nf], af[mf], bf[nf], c[mf][nf]);
        }
        __syncthreads();
    }

    // Epilogue. Thread quad geometry: rows r = (lane>>2)+8i, col c4=(lane&3)*4.
    // Row group i (8 rows) == 8-row chunk (chA + i); chA is a multiple of 4.
    const int c4 = (lane & 3) << 2;
    const int bb = m0 >> 12;                        // batch
    const int chA = ((m0 & (NN - 1)) + wm) >> 3;    // first 8-row chunk of warp tile
    float* stage = reinterpret_cast<float*>(smem_all) + warp * (32 * 20);

    #pragma unroll
    for (int nf = 0; nf < NF; nf++) {
        wmma::store_matrix_sync(stage,           c[0][nf], 20, wmma::mem_row_major);
        wmma::store_matrix_sync(stage + 16 * 20, c[1][nf], 20, wmma::mem_row_major);
        __syncwarp();
        float vv4[4][4];
        #pragma unroll
        for (int i = 0; i < 4; i++) {
            int r = (lane >> 2) + 8 * i;     // 0..31
            float4 v = *reinterpret_cast<float4*>(&stage[r * 20 + c4]);
            float* vv = vv4[i];
            vv[0] = v.x; vv[1] = v.y; vv[2] = v.z; vv[3] = v.w;
            #pragma unroll
            for (int t = 0; t < 4; t++)
                vv[t] += bias[j0 + wn + nf * 16 + c4 + t];
            if (op == 1) {
                #pragma unroll
                for (int t = 0; t < 4; t++) vv[t] = sigmoid_f(vv[t]);
            } else if (op == 2) {
                float e0 = gelu_exact(vv[0]), e1 = gelu_exact(vv[1]);
                float e2 = gelu_exact(vv[2]), e3 = gelu_exact(vv[3]);
                vv[0] = e0; vv[1] = e0 * e1;   // (lo, lo*hi) pairs
                vv[2] = e2; vv[3] = e2 * e3;
            }
            OutT* dst = &out[(size_t)(m0 + wm + r) * ldo + j0 + wn + nf * 16 + c4];
            if (sizeof(OutT) == 2) {
                __half2 h0 = __floats2half2_rn(vv[0], vv[1]);
                __half2 h1 = __floats2half2_rn(vv[2], vv[3]);
                uint2 u;
                u.x = *reinterpret_cast<unsigned*>(&h0);
                u.y = *reinterpret_cast<unsigned*>(&h1);
                *reinterpret_cast<uint2*>(dst) = u;
            } else {
                *reinterpret_cast<float4*>(dst) = make_float4(vv[0], vv[1], vv[2], vv[3]);
            }
        }
        if (op == 2) {
            // Per-8-row-chunk column sums: row group i = chunk chA+i.
            float s[4][4];
            #pragma unroll
            for (int i = 0; i < 4; i++)
                #pragma unroll
                for (int t = 0; t < 4; t++)
                    s[i][t] = vv4[i][t];
            #pragma unroll
            for (int mk = 4; mk <= 16; mk <<= 1)
                #pragma unroll
                for (int i = 0; i < 4; i++)
                    #pragma unroll
                    for (int t = 0; t < 4; t++)
                        s[i][t] += __shfl_xor_sync(0xFFFFFFFFu, s[i][t], mk);
            if ((lane >> 2) == 0) {          // lanes 0..3 hold full 8-row sums
                int p0 = (j0 - 512) + wn + nf * 16 + c4;
                #pragma unroll
                for (int t = 0; t < 4; t++) {
                    size_t gp = ((size_t)bb * DE + p0 + t) * NCHUNK;
                    // chunks chA..chA+3 are contiguous in c: one float4 store
                    *reinterpret_cast<float4*>(&g_part[gp + chA]) =
                        make_float4(s[0][t], s[1][t], s[2][t], s[3][t]);
                }
            }
        }
        __syncwarp();
    }
}

// ---------------------------------------------------------------------------
// Exclusive scan along c for each (b,p): one warp per (b,p), float4 loads.
// Lane owns 4 consecutive chunks; local 4-scan in regs, warp-scan the 4-sums.
// ---------------------------------------------------------------------------
__global__ __launch_bounds__(256) void scan_part_kernel() {
    const int w    = (blockIdx.x * 256 + threadIdx.x) >> 5;  // 0..2047 = (b,p)
    const int lane = threadIdx.x & 31;
    size_t base = (size_t)w * NCHUNK;

    float4 v[4];
    #pragma unroll
    for (int seg = 0; seg < 4; seg++)
        v[seg] = *reinterpret_cast<const float4*>(&g_part[base + seg * 128 + lane * 4]);

    float carry = 0.0f;
    #pragma unroll
    for (int seg = 0; seg < 4; seg++) {
        float t  = v[seg].x + v[seg].y + v[seg].z + v[seg].w;  // local total
        float x  = t;
        #pragma unroll
        for (int off = 1; off < 32; off <<= 1) {
            float y = __shfl_up_sync(0xFFFFFFFFu, x, off);
            if (lane >= off) x += y;
        }
        float base_ex = carry + x - t;      // exclusive prefix of this lane's 4
        float4 o;
        o.x = base_ex;
        o.y = base_ex + v[seg].x;
        o.z = o.y     + v[seg].y;
        o.w = o.z     + v[seg].z;
        *reinterpret_cast<float4*>(&g_part[base + seg * 128 + lane * 4]) = o;
        carry += __shfl_sync(0xFFFFFFFFu, x, 31);
    }
}

// ---------------------------------------------------------------------------
// Pass B: SINGLE-PASS apply (R15 geometry). Block = 16 rows = 2 chunks of 8.
// grp = tid>>7 selects the chunk; thread d=tid&127 owns channels 4d..4d+3.
// No smem, no sync: offsets direct from g_part; walk 8 rows accumulating.
// ---------------------------------------------------------------------------
__global__ __launch_bounds__(256) void scan_apply_kernel() {
    const int blk = blockIdx.x;            // 0..1023
    const int b   = blk >> 8;              // / 256 segments
    const int seg = blk & 255;             // 16-row segment
    const int d   = threadIdx.x & 127;     // channels p = 4d..4d+3
    const int grp = threadIdx.x >> 7;      // chunk within segment
    const int ch  = seg * 2 + grp;         // global 8-row chunk

    // Exclusive chunk offsets (4 scalar loads, issued early).
    size_t pb = ((size_t)b * DE + 4 * d) * NCHUNK + ch;
    float4 off;
    off.x = g_part[pb];
    off.y = g_part[pb + NCHUNK];
    off.z = g_part[pb + 2 * (size_t)NCHUNK];
    off.w = g_part[pb + 3 * (size_t)NCHUNK];

    const int n0 = ch * CHUNK;
    size_t rowbase = ((size_t)(b * NN + n0)) * 1024;
    float4 run = {0.f, 0.f, 0.f, 0.f};
    #pragma unroll
    for (int r = 0; r < 8; r++) {
        size_t ro = rowbase + (size_t)r * 1024;
        uint2 u  = *reinterpret_cast<const uint2*>(&g_sh_h[ro + 512 + 4 * d]);
        uint2 ug = *reinterpret_cast<const uint2*>(&g_sh_h[ro + 4 * d]);
        float2 f0 = __half22float2(*reinterpret_cast<__half2*>(&u.x));
        float2 f1 = __half22float2(*reinterpret_cast<__half2*>(&u.y));
        run.x += f0.x; run.y += f0.y; run.z += f1.x; run.w += f1.y;

        float rec = 1.0f / ((float)(n0 + r + 1) + 1e-7f);
        float2 G0 = __half22float2(*reinterpret_cast<__half2*>(&ug.x));
        float2 G1 = __half22float2(*reinterpret_cast<__half2*>(&ug.y));
        float o0 = G0.x * (off.x + run.x) * rec;
        float o1 = G0.y * (off.y + run.y) * rec;
        float o2 = G1.x * (off.z + run.z) * rec;
        float o3 = G1.y * (off.w + run.w) * rec;
        __half2 h0 = __floats2half2_rn(o0, o1);
        __half2 h1 = __floats2half2_rn(o2, o3);
        uint2 uo;
        uo.x = *reinterpret_cast<unsigned*>(&h0);
        uo.y = *reinterpret_cast<unsigned*>(&h1);
        *reinterpret_cast<uint2*>(&g_o_h[(size_t)(b * NN + n0 + r) * DE + 4 * d]) = uo;
    }
}

// ---------------------------------------------------------------------------
// Launcher
// ---------------------------------------------------------------------------
extern "C" void kernel_launch(void* const* d_in, const int* in_sizes, int n_in,
                              void* d_out, int out_size) {
    const float* xq   = (const float*)d_in[0];
    const float* W_se = (const float*)d_in[2];
    const float* b_se = (const float*)d_in[3];
    const float* W_po = (const float*)d_in[4];
    const float* b_po = (const float*)d_in[5];
    const float* W_ag = (const float*)d_in[6];
    const float* b_ag = (const float*)d_in[7];
    float* out = (float*)d_out;

    __half* shh_ptr = nullptr;
    __half* oh_ptr  = nullptr;
    __half* xqh_ptr = nullptr;
    __half* w1_ptr  = nullptr;
    __half* w3_ptr  = nullptr;
    float*  b1_ptr  = nullptr;
    cudaGetSymbolAddress((void**)&shh_ptr, g_sh_h);
    cudaGetSymbolAddress((void**)&oh_ptr,  g_o_h);
    cudaGetSymbolAddress((void**)&xqh_ptr, g_xq_h);
    cudaGetSymbolAddress((void**)&w1_ptr,  g_w1_h);
    cudaGetSymbolAddress((void**)&w3_ptr,  g_w3_h);
    cudaGetSymbolAddress((void**)&b1_ptr,  g_b1);

    // fp16 conversions + channel permutation (one launch)
    conv_all_kernel<<<(TOT * DIMV) / 1024, 256>>>(xq, W_se, W_po, W_ag, b_se, b_po);

    // GEMM1+2 fused: gate | combined-gelu (fp16, permuted), + 8-row chunk sums
    {
        dim3 grid(TOT / BM, 1024 / 128);   // (128, 8)
        gemm_f16_kernel<128, 2, __half><<<grid, 256>>>(
            xqh_ptr, DIMV,
            w1_ptr, b1_ptr,
            /*op0=*/1, /*op1=*/2, /*opSplit=*/DE, /*K=*/DIMV,
            shh_ptr, /*ldo=*/1024);
    }

    scan_part_kernel<<<(BB * DE * 32) / 256, 256>>>();   // 256 blocks, warp/(b,p)
    scan_apply_kernel<<<BB * (NN / 16), 256>>>();        // 1024 blocks, single-pass

    // GEMM3: [16384,512] x [128,512]^T -> out (fp32); W_ag K-dim permuted
    {
        dim3 grid(TOT / BM, DIMV / 64);    // (128, 2)
        gemm_f16_kernel<64, 3, float><<<grid, 256>>>(
            oh_ptr, DE,
            w3_ptr, b_ag,
            /*op0=*/0, /*op1=*/0, /*opSplit=*/1 << 30, /*K=*/DE,
            out, /*ldo=*/DIMV);
    }
}